// round 2
// baseline (speedup 1.0000x reference)
#include <cuda_runtime.h>

#define B_    512
#define MIN_  1024      // n_in
#define M_    1026      // n_in + 2
#define N_    512
#define T_    32
#define BT_   16384     // B_*T_
#define GMINF 0.01f
#define GMAXF 10.0f
#define PGMINF 0.1f
#define ZLEN  (B_*N_*T_)   // 8388608

// ---------------- scratch (static device globals; no allocation) ----------------
__device__ float g_V[MIN_*N_];      // theta_q / S       [m][n]
__device__ float g_H[MIN_*N_];      // g_tilde*(pos-neg) [m][n]
__device__ float g_bz[N_], g_by[N_];
__device__ float g_Gn[N_];          // sum_{m<=1024} g_tilde*neg_d
__device__ float g_Gcol[N_];        // sum_{all m} g_tilde
__device__ float g_Sx[MIN_], g_Sxx[MIN_];
__device__ float g_z [ZLEN];
__device__ float g_y2[ZLEN];
__device__ double g_termA, g_T1, g_SyyG, g_ZcG;

// ---------------- helpers ----------------
__device__ __forceinline__ float blockSum256(float v, volatile float* sm) {
    int tid = threadIdx.x;
    #pragma unroll
    for (int o = 16; o > 0; o >>= 1) v += __shfl_down_sync(0xffffffffu, v, o);
    if ((tid & 31) == 0) sm[tid >> 5] = v;
    __syncthreads();
    float r = 0.f;
    if (tid == 0) { for (int i = 0; i < 8; i++) r += sm[i]; }
    __syncthreads();
    return r;   // valid on tid 0
}

__device__ __forceinline__ float blockMin256(float v, volatile float* sm) {
    int tid = threadIdx.x;
    #pragma unroll
    for (int o = 16; o > 0; o >>= 1) v = fminf(v, __shfl_down_sync(0xffffffffu, v, o));
    if ((tid & 31) == 0) sm[tid >> 5] = v;
    __syncthreads();
    float r = 1e30f;
    if (tid == 0) { for (int i = 0; i < 8; i++) r = fminf(r, sm[i]); }
    __syncthreads();
    return r;   // valid on tid 0
}

__device__ __forceinline__ float tanh_fast(float v) {
    // tanh(v) = 1 - 2/(exp(2v)+1); __expf overflow -> inf -> result 1 (correct limit)
    float e = __expf(2.f * v);
    return 1.f - __fdividef(2.f, e + 1.f);
}

// ---------------- K0: zero scalar accumulators (graph-replay safe) ----------------
__global__ void zero_kernel() {
    g_termA = 0.0; g_T1 = 0.0; g_SyyG = 0.0; g_ZcG = 0.0;
}

// ---------------- K1: per-m stats of x: Sx[m], Sxx[m] ----------------
__global__ void xstats_kernel(const float* __restrict__ x) {
    int m = blockIdx.x;
    __shared__ float sm[8];
    const float* xm = x + (size_t)m * T_;
    float sx = 0.f, sxx = 0.f;
    for (int i = threadIdx.x; i < BT_; i += 256) {
        int b = i >> 5, t = i & 31;
        float v = xm[(size_t)b * (MIN_ * T_) + t];
        sx += v; sxx += v * v;
    }
    sx  = blockSum256(sx, sm);
    sxx = blockSum256(sxx, sm);
    if (threadIdx.x == 0) { g_Sx[m] = sx; g_Sxx[m] = sxx; }
}

// ---------------- K2: per-column theta processing ----------------
__global__ void setup_kernel(const float* __restrict__ theta) {
    int n = blockIdx.x;
    int tid = threadIdx.x;
    __shared__ float sm[8];
    __shared__ float bc[2];

    // pass A: S[n] = sum |theta_q|, min |theta_| over m
    float s = 0.f, mn = 1e30f;
    for (int m = tid; m < M_; m += 256) {
        float th  = theta[(size_t)m * N_ + n];
        float thc = fminf(fmaxf(th, -GMAXF), GMAXF);
        float thq = (fabsf(thc) < GMINF) ? 0.f : thc;
        s += fabsf(thq);
        mn = fminf(mn, fabsf(th));
    }
    float S  = blockSum256(s, sm);
    float MV = blockMin256(mn, sm);
    if (tid == 0) { bc[0] = S; bc[1] = MV; }
    __syncthreads();
    float invS   = 1.f / bc[0];
    float gscale = PGMINF / bc[1];

    // pass B: V, H, biases, column sums, termA contribution
    float bz = 0.f, gn = 0.f, gcol = 0.f, ta = 0.f;
    for (int m = tid; m < M_; m += 256) {
        float th  = theta[(size_t)m * N_ + n];
        float thc = fminf(fmaxf(th, -GMAXF), GMAXF);
        float thq = (fabsf(thc) < GMINF) ? 0.f : thc;
        bool  pos = (thq >= 0.f);
        float V   = thq * invS;
        float g   = fabsf(th) * gscale;
        float Hh  = pos ? g : -g;
        gcol += g;
        if (m < MIN_) {
            g_V[(size_t)m * N_ + n] = V;
            g_H[(size_t)m * N_ + n] = Hh;
            float sxx = g_Sxx[m];
            float snn = (float)BT_ - 2.f * g_Sx[m] + sxx;
            if (pos) { ta += g * sxx; }
            else     { ta += g * snn; bz += -V; gn += g; }
        } else if (m == MIN_) {          // ones row (index 1024)
            if (pos) { bz += V; ta += g * (float)BT_; }
            else     { gn += g; }        // Snn for this row is 0
            g_by[n] = Hh;
        }
        // m == 1025 (zeros row): Sxx=Snn=0, x_ext=x_neg=0 -> only gcol
    }
    bz   = blockSum256(bz, sm);
    gn   = blockSum256(gn, sm);
    gcol = blockSum256(gcol, sm);
    ta   = blockSum256(ta, sm);
    if (tid == 0) {
        g_bz[n] = bz; g_Gn[n] = gn; g_Gcol[n] = gcol;
        atomicAdd(&g_termA, (double)ta);
    }
}

// ---------------- K3: the GEMM  out[b,n,t] = sum_m x[b,m,t]*Wt[m,n] + bias[n] ----------------
// grid (512, 2): blockIdx.x = b, blockIdx.y selects (V -> z) or (H -> y2)
__global__ __launch_bounds__(256) void gemm_kernel(const float* __restrict__ x) {
    int b    = blockIdx.x;
    int wsel = blockIdx.y;
    const float* __restrict__ Wt   = wsel ? g_H  : g_V;
    const float* __restrict__ bias = wsel ? g_by : g_bz;
    float* __restrict__ out        = wsel ? g_y2 : g_z;

    __shared__ float ws[16][512];
    __shared__ float xs[16][32];

    int tid = threadIdx.x;
    int tn = tid >> 2, tt = tid & 3;
    int n0 = tn * 8, t0 = tt * 8;

    float acc[8][8];
    #pragma unroll
    for (int i = 0; i < 8; i++)
        #pragma unroll
        for (int j = 0; j < 8; j++) acc[i][j] = 0.f;

    const float* xb = x + (size_t)b * (MIN_ * T_);

    for (int mc = 0; mc < MIN_; mc += 16) {
        // stage weights: 16x512 floats
        #pragma unroll
        for (int i = 0; i < 8; i++) {
            int idx = tid + i * 256;          // 0..2047 float4s
            int r = idx >> 7, c4 = idx & 127;
            *(float4*)&ws[r][c4 * 4] =
                *(const float4*)&Wt[(size_t)(mc + r) * N_ + c4 * 4];
        }
        // stage x: 16x32 floats
        if (tid < 128) {
            int r = tid >> 3, c4 = tid & 7;
            *(float4*)&xs[r][c4 * 4] =
                *(const float4*)&xb[(size_t)(mc + r) * T_ + c4 * 4];
        }
        __syncthreads();

        #pragma unroll
        for (int k = 0; k < 16; k++) {
            float4 a0 = *(float4*)&xs[k][t0];
            float4 a1 = *(float4*)&xs[k][t0 + 4];
            float4 w0 = *(float4*)&ws[k][n0];
            float4 w1 = *(float4*)&ws[k][n0 + 4];
            float av[8] = {a0.x, a0.y, a0.z, a0.w, a1.x, a1.y, a1.z, a1.w};
            float wv[8] = {w0.x, w0.y, w0.z, w0.w, w1.x, w1.y, w1.z, w1.w};
            #pragma unroll
            for (int i = 0; i < 8; i++)
                #pragma unroll
                for (int j = 0; j < 8; j++)
                    acc[i][j] += wv[i] * av[j];
        }
        __syncthreads();
    }

    #pragma unroll
    for (int i = 0; i < 8; i++) {
        float bb = bias[n0 + i];
        float* op = out + ((size_t)b * N_ + n0 + i) * T_ + t0;
        float4 o0 = make_float4(acc[i][0] + bb, acc[i][1] + bb, acc[i][2] + bb, acc[i][3] + bb);
        float4 o1 = make_float4(acc[i][4] + bb, acc[i][5] + bb, acc[i][6] + bb, acc[i][7] + bb);
        *(float4*)op       = o0;
        *(float4*)(op + 4) = o1;
    }
}

// ---------------- K4: SG pointwise MLP + scalar reductions ----------------
__global__ void epilogue_kernel(const float* __restrict__ w1p, const float* __restrict__ b1p,
                                const float* __restrict__ w2p, const float* __restrict__ b2p,
                                float* __restrict__ aout) {
    int b = blockIdx.x;
    int tid = threadIdx.x;
    __shared__ float sm[8];
    __shared__ float w1[8], b1[8], w2[8], b2s[1];
    if (tid < 8) { w1[tid] = w1p[tid]; b1[tid] = b1p[tid]; w2[tid] = w2p[tid]; }
    if (tid == 0) b2s[0] = b2p[0];
    __syncthreads();

    float t1 = 0.f, syyg = 0.f, zcg = 0.f;
    #pragma unroll
    for (int nn = 0; nn < 2; nn++) {
        int n = tid * 2 + nn;
        const float* zp = g_z  + ((size_t)b * N_ + n) * T_;
        const float* yp = g_y2 + ((size_t)b * N_ + n) * T_;
        float*       ap = aout + ((size_t)b * N_ + n) * T_;
        float syy = 0.f, zc = 0.f;
        #pragma unroll 4
        for (int t = 0; t < T_; t++) {
            float z = zp[t], y = yp[t];
            t1  += z * y;
            syy += z * z;
            zc  += z;
            float o = b2s[0];
            #pragma unroll
            for (int j = 0; j < 8; j++)
                o += tanh_fast(fmaf(z, w1[j], b1[j])) * w2[j];
            ap[t] = __fdividef(1.f, 1.f + __expf(-o));
        }
        syyg += syy * g_Gcol[n];
        zcg  += zc  * g_Gn[n];
    }
    t1   = blockSum256(t1, sm);
    syyg = blockSum256(syyg, sm);
    zcg  = blockSum256(zcg, sm);
    if (tid == 0) {
        atomicAdd(&g_T1,   (double)t1);
        atomicAdd(&g_SyyG, (double)syyg);
        atomicAdd(&g_ZcG,  (double)zcg);
    }
}

// ---------------- K5: power ----------------
__global__ void finalize_kernel(float* __restrict__ out) {
    double p = (g_termA - 2.0 * (g_T1 + g_ZcG) + g_SyyG) / (double)BT_;
    out[ZLEN] = (float)p;
}

// ---------------- launch ----------------
extern "C" void kernel_launch(void* const* d_in, const int* in_sizes, int n_in,
                              void* d_out, int out_size) {
    const float* x     = (const float*)d_in[0];
    const float* theta = (const float*)d_in[1];
    const float* w1    = (const float*)d_in[2];
    const float* b1    = (const float*)d_in[3];
    const float* w2    = (const float*)d_in[4];
    const float* b2    = (const float*)d_in[5];
    float* out = (float*)d_out;

    zero_kernel<<<1, 1>>>();
    xstats_kernel<<<MIN_, 256>>>(x);
    setup_kernel<<<N_, 256>>>(theta);
    gemm_kernel<<<dim3(B_, 2), 256>>>(x);
    epilogue_kernel<<<B_, 256>>>(w1, b1, w2, b2, out);
    finalize_kernel<<<1, 1>>>(out);
}

// round 5
// speedup vs baseline: 5.1557x; 5.1557x over previous
#include <cuda_runtime.h>
#include <cuda_bf16.h>
#include <cstdint>

#define B_    512
#define MIN_  1024      // n_in (GEMM K)
#define N_    512
#define T_    32
#define BT_   16384
#define GMINF 0.01f
#define GMAXF 10.0f
#define PGMINF 0.1f
#define ZLEN  (B_*N_*T_)

#define NT_   64            // n rows per CTA
#define CT_   128           // cols per CTA (col = b*32+t)
#define KCH   64            // K chunk (64 bf16 = 128B row)
#define NCHUNK (MIN_/KCH)   // 16
#define STAGES 3
#define AV_OFF 0
#define AH_OFF 8192
#define BB_OFF 16384
#define STAGE_BYTES 32768   // 64*128 + 64*128 + 128*128
#define SMEM_DYN (STAGES*STAGE_BYTES)

// ---------------- scratch ----------------
__device__ __align__(16) __nv_bfloat16 g_Wb[2u*N_*MIN_];         // [V|H][n][m] K-major
__device__ __align__(16) __nv_bfloat16 g_xT[(size_t)B_*T_*MIN_]; // [(b*32+t)][m] K-major
__device__ float g_bz[N_], g_by[N_], g_Gn[N_], g_Gcol[N_];
__device__ float g_Sx[MIN_], g_Sxx[MIN_];
__device__ double g_termA, g_T1, g_SyyG, g_ZcG;

// ---------------- ptx helpers ----------------
__device__ __forceinline__ uint32_t s2u(const void* p) {
    uint32_t a;
    asm("{ .reg .u64 t; cvta.to.shared.u64 t, %1; cvt.u32.u64 %0, t; }" : "=r"(a) : "l"(p));
    return a;
}

#define CPA16(dst, src) \
    asm volatile("cp.async.cg.shared.global [%0], [%1], 16;" :: "r"(dst), "l"(src) : "memory")
#define CPA_COMMIT() asm volatile("cp.async.commit_group;" ::: "memory")

#define LDSM_X4(r0, r1, r2, r3, a) \
    asm volatile("ldmatrix.sync.aligned.m8n8.x4.shared.b16 {%0,%1,%2,%3}, [%4];" \
        : "=r"(r0), "=r"(r1), "=r"(r2), "=r"(r3) : "r"(a))

#define MMA16816(d, a0, a1, a2, a3, b0, b1) \
    asm volatile("mma.sync.aligned.m16n8k16.row.col.f32.bf16.bf16.f32 " \
        "{%0,%1,%2,%3},{%4,%5,%6,%7},{%8,%9},{%0,%1,%2,%3};" \
        : "+f"((d)[0]), "+f"((d)[1]), "+f"((d)[2]), "+f"((d)[3]) \
        : "r"(a0), "r"(a1), "r"(a2), "r"(a3), "r"(b0), "r"(b1))

// ---------------- math helpers ----------------
__device__ __forceinline__ float blockSum256(float v, volatile float* sm) {
    int tid = threadIdx.x;
    #pragma unroll
    for (int o = 16; o > 0; o >>= 1) v += __shfl_down_sync(0xffffffffu, v, o);
    if ((tid & 31) == 0) sm[tid >> 5] = v;
    __syncthreads();
    float r = 0.f;
    if (tid == 0) { for (int i = 0; i < 8; i++) r += sm[i]; }
    __syncthreads();
    return r;
}
__device__ __forceinline__ float blockMin256(float v, volatile float* sm) {
    int tid = threadIdx.x;
    #pragma unroll
    for (int o = 16; o > 0; o >>= 1) v = fminf(v, __shfl_down_sync(0xffffffffu, v, o));
    if ((tid & 31) == 0) sm[tid >> 5] = v;
    __syncthreads();
    float r = 1e30f;
    if (tid == 0) { for (int i = 0; i < 8; i++) r = fminf(r, sm[i]); }
    __syncthreads();
    return r;
}
__device__ __forceinline__ float tanh_hw(float v) {
    float r;
    asm("tanh.approx.f32 %0, %1;" : "=f"(r) : "f"(v));
    return r;
}

// ---------------- K0: zero accumulators ----------------
__global__ void zero_kernel() {
    int i = threadIdx.x + blockIdx.x * 256;
    if (i < MIN_) { g_Sx[i] = 0.f; g_Sxx[i] = 0.f; }
    if (i == 0) { g_termA = 0.0; g_T1 = 0.0; g_SyyG = 0.0; g_ZcG = 0.0; }
}

// ---------------- K1: transpose x -> bf16 xT[(b,t)][m], fused Sx/Sxx ----------------
__global__ __launch_bounds__(256) void prep_kernel(const float* __restrict__ x) {
    __shared__ float sx[64][33];
    __shared__ float pSx[64], pSxx[64];
    int b = blockIdx.x, m0 = blockIdx.y * 64;
    int tid = threadIdx.x;
    if (tid < 64) { pSx[tid] = 0.f; pSxx[tid] = 0.f; }
    __syncthreads();
    const float* xb = x + (size_t)b * (MIN_ * T_) + (size_t)m0 * T_;
    #pragma unroll
    for (int i = 0; i < 2; i++) {
        int f = tid + i * 256;
        int r = f >> 3, t4 = f & 7;
        float4 v = *(const float4*)(xb + r * T_ + t4 * 4);
        sx[r][t4 * 4 + 0] = v.x; sx[r][t4 * 4 + 1] = v.y;
        sx[r][t4 * 4 + 2] = v.z; sx[r][t4 * 4 + 3] = v.w;
        atomicAdd(&pSx[r],  v.x + v.y + v.z + v.w);
        atomicAdd(&pSxx[r], v.x * v.x + v.y * v.y + v.z * v.z + v.w * v.w);
    }
    __syncthreads();
    if (tid < 64) {
        atomicAdd(&g_Sx[m0 + tid],  pSx[tid]);
        atomicAdd(&g_Sxx[m0 + tid], pSxx[tid]);
    }
    int t = tid >> 3, seg = tid & 7;
    __align__(16) __nv_bfloat16 tmp[8];
    #pragma unroll
    for (int j = 0; j < 8; j++) tmp[j] = __float2bfloat16(sx[seg * 8 + j][t]);
    *(uint4*)(&g_xT[((size_t)(b * T_ + t)) * MIN_ + m0 + seg * 8]) = *(uint4*)tmp;
}

// ---------------- K2: per-column theta processing ----------------
__global__ void setup_kernel(const float* __restrict__ theta) {
    int n = blockIdx.x;
    int tid = threadIdx.x;
    __shared__ float sm[8];
    __shared__ float bc[2];

    float s = 0.f, mn = 1e30f;
    for (int m = tid; m < MIN_ + 2; m += 256) {
        float th  = theta[(size_t)m * N_ + n];
        float thc = fminf(fmaxf(th, -GMAXF), GMAXF);
        float thq = (fabsf(thc) < GMINF) ? 0.f : thc;
        s += fabsf(thq);
        mn = fminf(mn, fabsf(th));
    }
    float S  = blockSum256(s, sm);
    float MV = blockMin256(mn, sm);
    if (tid == 0) { bc[0] = S; bc[1] = MV; }
    __syncthreads();
    float invS   = 1.f / bc[0];
    float gscale = PGMINF / bc[1];

    float bz = 0.f, gn = 0.f, gcol = 0.f, ta = 0.f;
    for (int m = tid; m < MIN_ + 2; m += 256) {
        float th  = theta[(size_t)m * N_ + n];
        float thc = fminf(fmaxf(th, -GMAXF), GMAXF);
        float thq = (fabsf(thc) < GMINF) ? 0.f : thc;
        bool  pos = (thq >= 0.f);
        float V   = thq * invS;
        float g   = fabsf(th) * gscale;
        float Hh  = pos ? g : -g;
        gcol += g;
        if (m < MIN_) {
            g_Wb[(size_t)n * MIN_ + m]        = __float2bfloat16(V);
            g_Wb[(size_t)(N_ + n) * MIN_ + m] = __float2bfloat16(Hh);
            float sxx = g_Sxx[m];
            float snn = (float)BT_ - 2.f * g_Sx[m] + sxx;
            if (pos) { ta += g * sxx; }
            else     { ta += g * snn; bz += -V; gn += g; }
        } else if (m == MIN_) {
            if (pos) { bz += V; ta += g * (float)BT_; }
            else     { gn += g; }
            g_by[n] = Hh;
        }
    }
    bz   = blockSum256(bz, sm);
    gn   = blockSum256(gn, sm);
    gcol = blockSum256(gcol, sm);
    ta   = blockSum256(ta, sm);
    if (tid == 0) {
        g_bz[n] = bz; g_Gn[n] = gn; g_Gcol[n] = gcol;
        atomicAdd(&g_termA, (double)ta);
    }
}

// ---------------- K3: mma.sync GEMM (V + H) + fused epilogue ----------------
__global__ __launch_bounds__(256, 2) void gemm_fused_kernel(
    float* __restrict__ out,
    const float* __restrict__ w1p, const float* __restrict__ b1p,
    const float* __restrict__ w2p, const float* __restrict__ b2p)
{
    extern __shared__ char dynsmem[];
    __shared__ float smred[8];
    __shared__ float w1[8], b1[8], w2[8], b2s[1];

    int tid = threadIdx.x;
    int wid = tid >> 5, lane = tid & 31;
    int wn = wid & 3, wc = wid >> 2;
    int col0 = blockIdx.x * CT_;
    int n0   = blockIdx.y * NT_;

    if (tid < 8) { w1[tid] = w1p[tid]; b1[tid] = b1p[tid]; w2[tid] = w2p[tid]; }
    if (tid == 0) b2s[0] = b2p[0];

    uint32_t dbase = s2u(dynsmem);

    const __nv_bfloat16* gA_V = g_Wb + (size_t)n0 * MIN_;
    const __nv_bfloat16* gB   = g_xT + (size_t)col0 * MIN_;

    // ldmatrix lane-constant address components
    int mat = lane >> 3, lr = lane & 7;
    uint32_t xorv = (uint32_t)lr << 4;
    int rA = wn * 16 + ((mat & 1) << 3) + lr;            // weight row (local n)
    uint32_t aSeg = (uint32_t)(mat >> 1) * 16;
    uint32_t avOff = AV_OFF + (uint32_t)rA * 128;
    uint32_t bSeg = (uint32_t)(mat & 1) * 16;
    uint32_t bOff[4];
    #pragma unroll
    for (int bb = 0; bb < 4; bb++) {
        int rB = wc * 64 + bb * 16 + ((mat >> 1) << 3) + lr;   // local col
        bOff[bb] = BB_OFF + (uint32_t)rB * 128;
    }

    float accV[8][4], accH[8][4];
    #pragma unroll
    for (int i = 0; i < 8; i++)
        #pragma unroll
        for (int j = 0; j < 4; j++) { accV[i][j] = 0.f; accH[i][j] = 0.f; }

    // cp.async fill for one chunk (all 256 threads)
    auto issue = [&](int c) {
        uint32_t st = dbase + (uint32_t)(c % STAGES) * STAGE_BYTES;
        int koff = c * KCH;
        #pragma unroll
        for (int i = 0; i < 8; i++) {
            int u = tid + i * 256;                 // 0..2047
            int region = u >> 9;                   // 0: A_V, 1: A_H, >=2: B
            int v = u & 511;
            if (region == 0) {
                int r = v >> 3, seg = v & 7;
                uint32_t sw = (uint32_t)r * 128 + (((uint32_t)seg * 16) ^ (((uint32_t)r & 7) << 4));
                CPA16(st + AV_OFF + sw, gA_V + (size_t)r * MIN_ + koff + seg * 8);
            } else if (region == 1) {
                int r = v >> 3, seg = v & 7;
                uint32_t sw = (uint32_t)r * 128 + (((uint32_t)seg * 16) ^ (((uint32_t)r & 7) << 4));
                CPA16(st + AH_OFF + sw, gA_V + (size_t)(N_ * MIN_) + (size_t)r * MIN_ + koff + seg * 8);
            } else {
                int w = u - 1024;                  // 0..1023
                int r = w >> 3, seg = w & 7;
                uint32_t sw = (uint32_t)r * 128 + (((uint32_t)seg * 16) ^ (((uint32_t)r & 7) << 4));
                CPA16(st + BB_OFF + sw, gB + (size_t)r * MIN_ + koff + seg * 8);
            }
        }
        CPA_COMMIT();
    };

    issue(0);
    issue(1);

    for (int c = 0; c < NCHUNK; c++) {
        if (c + 2 < NCHUNK) issue(c + 2);
        if (c + 2 < NCHUNK)      asm volatile("cp.async.wait_group 2;" ::: "memory");
        else if (c + 1 < NCHUNK) asm volatile("cp.async.wait_group 1;" ::: "memory");
        else                     asm volatile("cp.async.wait_group 0;" ::: "memory");
        __syncthreads();

        uint32_t st = dbase + (uint32_t)(c % STAGES) * STAGE_BYTES;
        #pragma unroll
        for (int kk = 0; kk < 4; kk++) {
            uint32_t ka = ((uint32_t)kk * 32 + aSeg) ^ xorv;
            uint32_t kb = ((uint32_t)kk * 32 + bSeg) ^ xorv;
            uint32_t aV0, aV1, aV2, aV3, aH0, aH1, aH2, aH3;
            LDSM_X4(aV0, aV1, aV2, aV3, st + avOff + ka);
            LDSM_X4(aH0, aH1, aH2, aH3, st + avOff + (AH_OFF - AV_OFF) + ka);
            #pragma unroll
            for (int bb = 0; bb < 4; bb++) {
                uint32_t b0, b1r, b2, b3;
                LDSM_X4(b0, b1r, b2, b3, st + bOff[bb] + kb);
                MMA16816(accV[bb * 2],     aV0, aV1, aV2, aV3, b0, b1r);
                MMA16816(accV[bb * 2 + 1], aV0, aV1, aV2, aV3, b2, b3);
                MMA16816(accH[bb * 2],     aH0, aH1, aH2, aH3, b0, b1r);
                MMA16816(accH[bb * 2 + 1], aH0, aH1, aH2, aH3, b2, b3);
            }
        }
        __syncthreads();
    }

    // ---------------- fused epilogue (registers -> out + reductions) ----------------
    int r0 = n0 + wn * 16 + (lane >> 2);         // global n of acc rows 0,1
    int r8 = r0 + 8;                             // global n of acc rows 2,3
    float bz0 = g_bz[r0], bz8 = g_bz[r8];
    float by0 = g_by[r0], by8 = g_by[r8];
    float gc0 = g_Gcol[r0], gc8 = g_Gcol[r8];
    float gn0 = g_Gn[r0], gn8 = g_Gn[r8];

    float t1 = 0.f, syyg = 0.f, zcg = 0.f;

    #pragma unroll
    for (int nf = 0; nf < 8; nf++) {
        int c0 = col0 + wc * 64 + nf * 8 + (lane & 3) * 2;   // global col (even)
        int b = c0 >> 5, t = c0 & 31;
        #pragma unroll
        for (int half = 0; half < 2; half++) {
            int r = half ? r8 : r0;
            float bzv = half ? bz8 : bz0, byv = half ? by8 : by0;
            float gcv = half ? gc8 : gc0, gnv = half ? gn8 : gn0;
            float z0 = accV[nf][half * 2 + 0] + bzv;
            float z1 = accV[nf][half * 2 + 1] + bzv;
            float y0 = accH[nf][half * 2 + 0] + byv;
            float y1 = accH[nf][half * 2 + 1] + byv;
            t1   += z0 * y0 + z1 * y1;
            syyg += (z0 * z0 + z1 * z1) * gcv;
            zcg  += (z0 + z1) * gnv;
            float o0 = b2s[0], o1 = b2s[0];
            #pragma unroll
            for (int k = 0; k < 8; k++) {
                o0 += tanh_hw(fmaf(z0, w1[k], b1[k])) * w2[k];
                o1 += tanh_hw(fmaf(z1, w1[k], b1[k])) * w2[k];
            }
            float a0 = __fdividef(1.f, 1.f + __expf(-o0));
            float a1 = __fdividef(1.f, 1.f + __expf(-o1));
            *(float2*)(out + ((size_t)b * N_ + r) * T_ + t) = make_float2(a0, a1);
        }
    }

    t1   = blockSum256(t1, smred);
    syyg = blockSum256(syyg, smred);
    zcg  = blockSum256(zcg, smred);
    if (tid == 0) {
        atomicAdd(&g_T1,   (double)t1);
        atomicAdd(&g_SyyG, (double)syyg);
        atomicAdd(&g_ZcG,  (double)zcg);
    }
}

// ---------------- K4: power ----------------
__global__ void finalize_kernel(float* __restrict__ out) {
    double p = (g_termA - 2.0 * (g_T1 + g_ZcG) + g_SyyG) / (double)BT_;
    out[ZLEN] = (float)p;
}

// ---------------- launch ----------------
extern "C" void kernel_launch(void* const* d_in, const int* in_sizes, int n_in,
                              void* d_out, int out_size) {
    const float* x     = (const float*)d_in[0];
    const float* theta = (const float*)d_in[1];
    const float* w1    = (const float*)d_in[2];
    const float* b1    = (const float*)d_in[3];
    const float* w2    = (const float*)d_in[4];
    const float* b2    = (const float*)d_in[5];
    float* out = (float*)d_out;

    cudaFuncSetAttribute(gemm_fused_kernel,
                         cudaFuncAttributeMaxDynamicSharedMemorySize, SMEM_DYN);

    zero_kernel<<<4, 256>>>();
    prep_kernel<<<dim3(B_, MIN_ / 64), 256>>>(x);
    setup_kernel<<<N_, 256>>>(theta);
    gemm_fused_kernel<<<dim3(BT_ / CT_, N_ / NT_), 256, SMEM_DYN>>>(out, w1, b1, w2, b2);
    finalize_kernel<<<1, 1>>>(out);
}